// round 16
// baseline (speedup 1.0000x reference)
#include <cuda_runtime.h>
#include <cstdint>

#define BB 8
#define CC 512
#define NNODES 2048
#define TT 24

#define K1_NC    4                          // n per chunk
#define K1_PITCH 96                         // words per c-row segment (4n*24t)
#define K1_TILE  (128*K1_PITCH)             // words per buffer (48 KB)
#define K1_SMEM  ((2*K1_TILE + 192) * 4)    // buffers + w2 slice + f1 stage + item

// k2b dynamic smem layout (floats): sf[512*26] | swx[32*65] | swy[32*65] | part(ull)[8*12*32]
#define K2B_SF    (512*26)
#define K2B_SWX   (K2B_SF)
#define K2B_SWY   (K2B_SWX + 32*65)
#define K2B_PART  (K2B_SWY + 32*65)
#define K2B_SMEM  ((K2B_PART + 8*12*32*2) * 4)

typedef unsigned long long ull;

// ---------------- scratch (static device arrays; no allocation) ----------------
__device__ float g_f1  [BB*TT*NNODES];   // f1[b][t][n]          (atomically accumulated)
__device__ float g_f2  [BB*CC*TT];       // f2[b][c][t]          (atomically accumulated)
__device__ float g_f2cT[BB*TT*CC];       // f2c transposed [b][t][c]   (plain stores)
__device__ float g_g   [BB*TT*CC];       // g[b][t][c] = f1c @ w       (red.v4 accumulated)
__device__ float g_s   [BB*TT*TT];       // sigmoid attention matrix
__device__ unsigned g_tick;              // k1 work ticket

// ---------------- packed f32x2 helpers ----------------
__device__ __forceinline__ ull fma2(ull a, ull b, ull c){
    ull d;
    asm("fma.rn.f32x2 %0, %1, %2, %3;" : "=l"(d) : "l"(a), "l"(b), "l"(c));
    return d;
}
__device__ __forceinline__ ull add2(ull a, ull b){
    ull d;
    asm("add.rn.f32x2 %0, %1, %2;" : "=l"(d) : "l"(a), "l"(b));
    return d;
}
__device__ __forceinline__ ull pack2(float f){
    ull r;
    asm("mov.b64 %0, {%1, %1};" : "=l"(r) : "f"(f));
    return r;
}
__device__ __forceinline__ float2 unpk2(ull v){
    float2 f;
    asm("mov.b64 {%0, %1}, %2;" : "=f"(f.x), "=f"(f.y) : "l"(v));
    return f;
}

// ---------------- K0: zero scratch (3 kernels; shifts k1 to capture slot) ----------------
__global__ void k0a_zero(){
    int idx = blockIdx.x * 256 + threadIdx.x;
    if (idx < BB*TT*NNODES) g_f1[idx] = 0.0f;
}
__global__ void k0b_zero(){
    int idx = blockIdx.x * 256 + threadIdx.x;
    if (idx < BB*CC*TT) g_f2[idx] = 0.0f;
}
__global__ void k0c_zero(){
    int idx = blockIdx.x * 256 + threadIdx.x;
    if (idx < BB*CC*TT) g_g[idx] = 0.0f;
    if (idx == 0) g_tick = 0u;
}

// ---------------- K1: fused dual weighted reduction, persistent + ticket ----------------
// grid = 296 (2/SM), block = 192. Work item = (b, ct, 64-n sweep); 1024 items.
// cp.async double-buffered chunks of (128c x 4n x 24t); XOR-swizzled smem tile.
__device__ __forceinline__ void k1_stage(const float* gbase, float* buf, int ju, int c0s){
#pragma unroll
    for (int k2 = 0; k2 < 16; ++k2){
        const int c = c0s + 8*k2;
        const float* g = gbase + (size_t)c * (NNODES*TT);
        unsigned sa = (unsigned)__cvta_generic_to_shared(
            &buf[c*K1_PITCH + ((ju ^ (c & 7)) << 2)]);
        asm volatile("cp.async.cg.shared.global [%0], [%1], 16;" :: "r"(sa), "l"(g) : "memory");
    }
    asm volatile("cp.async.commit_group;" ::: "memory");
}

__global__ void __launch_bounds__(192, 2)
k1_reduce(const float* __restrict__ seq, const float* __restrict__ w1, const float* __restrict__ w2){
    extern __shared__ float sm[];
    float* buf0 = sm;
    float* buf1 = sm + K1_TILE;
    float* sw2n = sm + 2*K1_TILE;      // [64]
    float* f1st = sw2n + 64;           // [96]
    unsigned* sitem = (unsigned*)(f1st + 96);

    const int tid = threadIdx.x;
    const int w   = tid >> 5;
    const int lane= tid & 31;
    const int ju  = tid % 24;
    const int c0s = tid / 24;
    const int xm  = lane & 7;

    for (;;){
        if (tid == 0) sitem[0] = atomicAdd(&g_tick, 1u);
        __syncthreads();               // broadcast item; also orders buffer/f1st reuse
        const unsigned item = sitem[0];
        if (item >= 1024u) break;

        const int b  = item >> 7;
        const int ct = (item >> 5) & 3;
        const int nb = (int)(item & 31u) * 64;

        if (tid < 64) sw2n[tid] = w2[nb + tid];

        const float* seqbase = seq + ((size_t)(b*CC + ct*128) * NNODES + nb) * TT + ju*4;

        ull w1p[4];
#pragma unroll
        for (int kk = 0; kk < 4; ++kk) w1p[kk] = pack2(w1[ct*128 + lane + 32*kk]);

        ull acc[4][2];
#pragma unroll
        for (int kk = 0; kk < 4; ++kk){ acc[kk][0] = 0ull; acc[kk][1] = 0ull; }

        k1_stage(seqbase, buf0, ju, c0s);

        for (int ch = 0; ch < 16; ++ch){
            float* cur = (ch & 1) ? buf1 : buf0;
            if (ch < 15){
                k1_stage(seqbase + (size_t)(ch+1)*K1_NC*TT, (ch & 1) ? buf0 : buf1, ju, c0s);
                asm volatile("cp.async.wait_group 1;" ::: "memory");
            } else {
                asm volatile("cp.async.wait_group 0;" ::: "memory");
            }
            __syncthreads();           // sync(A): buffer ready; prior f1st reads done

#pragma unroll
            for (int nn = 0; nn < K1_NC; ++nn){
                const ull w2p = pack2(sw2n[ch*K1_NC + nn]);
                const int u = 6*nn + w;
                const int so = ((u ^ xm) << 2);
                ull p0 = 0ull, p1 = 0ull;
#pragma unroll
                for (int kk = 0; kk < 4; ++kk){
                    const ulonglong2 x = *reinterpret_cast<const ulonglong2*>(
                        &cur[(lane + 32*kk)*K1_PITCH + so]);
                    acc[kk][0] = fma2(w2p, x.x, acc[kk][0]);
                    acc[kk][1] = fma2(w2p, x.y, acc[kk][1]);
                    p0 = fma2(w1p[kk], x.x, p0);
                    p1 = fma2(w1p[kk], x.y, p1);
                }
#pragma unroll
                for (int off = 16; off > 0; off >>= 1){
                    p0 = add2(p0, __shfl_xor_sync(0xffffffffu, p0, off));
                    p1 = add2(p1, __shfl_xor_sync(0xffffffffu, p1, off));
                }
                if (lane == 0){
                    float2 a = unpk2(p0), d = unpk2(p1);
                    *reinterpret_cast<float4*>(&f1st[nn*24 + w*4]) = make_float4(a.x, a.y, d.x, d.y);
                }
            }
            __syncthreads();           // sync(B): f1st complete, tile reads done

            if (tid < 96){
                const int nn = tid / 24, t = tid - nn*24;
                atomicAdd(&g_f1[((size_t)b*TT + t)*NNODES + nb + ch*K1_NC + nn], f1st[nn*24 + t]);
            }
        }

#pragma unroll
        for (int kk = 0; kk < 4; ++kk){
            const int c = ct*128 + lane + 32*kk;
            float* o = g_f2 + ((size_t)b*CC + c)*TT + w*4;
            float2 a = unpk2(acc[kk][0]), d = unpk2(acc[kk][1]);
            atomicAdd(o + 0, a.x);
            atomicAdd(o + 1, a.y);
            atomicAdd(o + 2, d.x);
            atomicAdd(o + 3, d.y);
        }
    }
}

// ---------------- K2b: dilated conv of f2 over t, ATOMIC-FREE (unchanged) ----------------
__global__ void __launch_bounds__(256) k2b_conv2(const float* __restrict__ Wd2){
    extern __shared__ float smb[];
    float* sf  = smb;                    // [512][26], j = t+1, halo at 0/25
    float* swx = smb + K2B_SWX;          // [32][65]
    float* swy = smb + K2B_SWY;          // [32][65]
    ull*   part= reinterpret_cast<ull*>(smb + K2B_PART);  // [8][12][32]

    const int b  = blockIdx.x >> 4;
    const int o0 = (blockIdx.x & 15) * 32;
    const int tid   = threadIdx.x;
    const int olane = tid & 31;
    const int ig    = tid >> 5;

    for (int i = tid; i < 512; i += 256){ sf[i*26] = 0.0f; sf[i*26 + 25] = 0.0f; }
    const float* f2b = g_f2 + (size_t)b*CC*TT;
#pragma unroll
    for (int u = 0; u < 48; ++u){
        int idx = tid + u*256;
        int i = idx / 24, t = idx - i*24;
        sf[i*26 + t + 1] = f2b[idx];
    }

    ull acc[12];
#pragma unroll
    for (int u = 0; u < 12; ++u) acc[u] = 0ull;

    const float2* wsrc = reinterpret_cast<const float2*>(Wd2);
    for (int r = 0; r < 8; ++r){
        __syncthreads();
#pragma unroll
        for (int u = 0; u < 8; ++u){
            int idx = tid + u*256;
            int oo = idx >> 6, iz = idx & 63;
            float2 wv = wsrc[(size_t)(o0+oo)*CC + r*64 + iz];
            swx[oo*65 + iz] = wv.x;
            swy[oo*65 + iz] = wv.y;
        }
        __syncthreads();
#pragma unroll
        for (int q = 0; q < 8; ++q){
            const int li = ig*8 + q;
            const int i  = r*64 + li;
            ull wx = pack2(swx[olane*65 + li]);
            ull wy = pack2(swy[olane*65 + li]);
            const ull* R = reinterpret_cast<const ull*>(&sf[i*26]);
#pragma unroll
            for (int u = 0; u < 12; ++u){
                acc[u] = fma2(wx, R[u], acc[u]);
                acc[u] = fma2(wy, R[u+1], acc[u]);
            }
        }
    }
    __syncthreads();
#pragma unroll
    for (int u = 0; u < 12; ++u) part[(ig*12 + u)*32 + olane] = acc[u];
    __syncthreads();
    const int oo = tid & 31;
    const int tb = (tid >> 5) * 3;
#pragma unroll
    for (int q = 0; q < 3; ++q){
        const int t = tb + q;
        const int ttp = t >> 1, half = t & 1;
        float s = 0.0f;
#pragma unroll
        for (int g2 = 0; g2 < 8; ++g2){
            float2 p = unpk2(part[(g2*12 + ttp)*32 + oo]);
            s += half ? p.y : p.x;
        }
        g_f2cT[(size_t)b*TT*CC + (size_t)t*CC + o0 + oo] = s;
    }
}

// ---------------- K2ac: FUSED dilated-conv(f1) + GEMM, cp.async-staged w ----------------
// sf2T transposed [nl][t] so per-q broadcasts are 6 LDS.128 instead of 12 LDS.64.
__global__ void __launch_bounds__(256, 2) k2ac_fused(const float* __restrict__ Wd1,
                                                     const float* __restrict__ w){
    __shared__ __align__(16) float pool[8192];   // phase1: s1|sw ; phase2: wbuf0|wbuf1
    __shared__ ull sf2T[64][26];                 // splatted f1c tile, [nl][t] (+pad)

    const int b  = blockIdx.x >> 5;
    const int n0 = (blockIdx.x & 31) * 64;
    const int tid = threadIdx.x;

    float* s1 = pool;                 // [24][66]
    float* sw = pool + TT*66;         // [24][48]

    for (int idx = tid; idx < TT*48; idx += 256) sw[idx] = Wd1[idx];
    for (int idx = tid; idx < TT*66; idx += 256){
        int i = idx / 66, j = idx - i*66;
        int n = n0 + j - 1;
        s1[i*66 + j] = (n >= 0 && n < NNODES) ? g_f1[((size_t)b*TT + i)*NNODES + n] : 0.0f;
    }
    __syncthreads();
#pragma unroll
    for (int u = 0; u < 6; ++u){
        int idx = tid + u*256;           // 0..1535
        int t = idx >> 6, nl = idx & 63;
        float acc = 0.0f;
#pragma unroll
        for (int i = 0; i < TT; ++i)
            acc += s1[i*66 + nl] * sw[t*48 + 2*i] + s1[i*66 + nl+2] * sw[t*48 + 2*i+1];
        sf2T[nl][t] = pack2(acc);
    }
    __syncthreads();                     // phase1 reads done -> pool reusable

    const int th = tid >> 7;             // t-half 0..1
    const int cq = tid & 127;            // c-quad
    ull acc[12][2];
#pragma unroll
    for (int tt = 0; tt < 12; ++tt){ acc[tt][0] = 0ull; acc[tt][1] = 0ull; }

    const float* wchunk = w + (size_t)n0*CC;

    // stage tile 0
#pragma unroll
    for (int u = 0; u < 4; ++u){
        int idx = tid + u*256;
        int rw = idx >> 7, c4 = idx & 127;
        unsigned sa = (unsigned)__cvta_generic_to_shared(&pool[rw*512 + c4*4]);
        asm volatile("cp.async.cg.shared.global [%0], [%1], 16;"
                     :: "r"(sa), "l"(wchunk + (size_t)rw*CC + c4*4) : "memory");
    }
    asm volatile("cp.async.commit_group;" ::: "memory");

    for (int r = 0; r < 8; ++r){
        const float* cur = (r & 1) ? (pool + 4096) : pool;
        if (r < 7){
            float* nxt = (r & 1) ? pool : (pool + 4096);
#pragma unroll
            for (int u = 0; u < 4; ++u){
                int idx = tid + u*256;
                int rw = idx >> 7, c4 = idx & 127;
                unsigned sa = (unsigned)__cvta_generic_to_shared(&nxt[rw*512 + c4*4]);
                asm volatile("cp.async.cg.shared.global [%0], [%1], 16;"
                             :: "r"(sa), "l"(wchunk + (size_t)((r+1)*8 + rw)*CC + c4*4) : "memory");
            }
            asm volatile("cp.async.commit_group;" ::: "memory");
            asm volatile("cp.async.wait_group 1;" ::: "memory");
        } else {
            asm volatile("cp.async.wait_group 0;" ::: "memory");
        }
        __syncthreads();                 // tile r visible to all
#pragma unroll
        for (int q = 0; q < 8; ++q){
            const ulonglong2 wp = *reinterpret_cast<const ulonglong2*>(&cur[q*512 + 4*cq]);
            const int nl = r*8 + q;
            const ulonglong2* fr = reinterpret_cast<const ulonglong2*>(&sf2T[nl][th*12]);
#pragma unroll
            for (int p = 0; p < 6; ++p){
                ulonglong2 fv = fr[p];       // LDS.128 broadcast
                acc[2*p  ][0] = fma2(fv.x, wp.x, acc[2*p  ][0]);
                acc[2*p  ][1] = fma2(fv.x, wp.y, acc[2*p  ][1]);
                acc[2*p+1][0] = fma2(fv.y, wp.x, acc[2*p+1][0]);
                acc[2*p+1][1] = fma2(fv.y, wp.y, acc[2*p+1][1]);
            }
        }
        __syncthreads();                 // compute done before next overwrite
    }

#pragma unroll
    for (int tt = 0; tt < 12; ++tt){
        float2 a = unpk2(acc[tt][0]), d = unpk2(acc[tt][1]);
        float* gp = &g_g[((size_t)b*TT + th*12 + tt)*CC + 4*cq];
        asm volatile("red.global.add.v4.f32 [%0], {%1,%2,%3,%4};"
                     :: "l"(gp), "f"(a.x), "f"(a.y), "f"(d.x), "f"(d.y) : "memory");
    }
}

// ---------------- K2d1: s[b,j,k] = sigmoid(g[b,j,:] . f2cT[b,k,:] + bias) ----------------
__global__ void __launch_bounds__(128) k2d1_attn(const float* __restrict__ bbias){
    const int b = blockIdx.x / 24;
    const int jj = blockIdx.x % 24;
    const int tid  = threadIdx.x;
    const int wrp  = tid >> 5;
    const int lane = tid & 31;
    __shared__ __align__(16) float sg[CC];
    const float* grow = g_g + ((size_t)b*TT + jj)*CC;
#pragma unroll
    for (int u = 0; u < 4; ++u) sg[tid + u*128] = grow[tid + u*128];
    __syncthreads();
    const ull* sg2 = reinterpret_cast<const ull*>(sg);
    const ull* f0  = reinterpret_cast<const ull*>(g_f2cT + ((size_t)b*TT + wrp*6)*CC);
    ull acc[6] = {0ull,0ull,0ull,0ull,0ull,0ull};
#pragma unroll
    for (int it = 0; it < 8; ++it){
        ull gv = sg2[lane + it*32];
#pragma unroll
        for (int kk = 0; kk < 6; ++kk)
            acc[kk] = fma2(f0[(size_t)kk*256 + lane + it*32], gv, acc[kk]);
    }
#pragma unroll
    for (int kk = 0; kk < 6; ++kk)
#pragma unroll
        for (int off = 16; off > 0; off >>= 1)
            acc[kk] = add2(acc[kk], __shfl_xor_sync(0xffffffffu, acc[kk], off));
    if (lane < 6){
        int k = wrp*6 + lane;
        float2 aa = unpk2(acc[lane]);
        float sv = aa.x + aa.y + bbias[jj*TT + k];
        g_s[((size_t)b*TT + jj)*TT + k] = 1.0f/(1.0f + __expf(-sv));
    }
}

// ---------------- K2d2: l = v @ s; BN + mask + softmax (single block) ----------------
__global__ void k2d2_final(const float* __restrict__ v, const float* __restrict__ gamma,
                           const float* __restrict__ beta, float* __restrict__ out){
    const int tid = threadIdx.x;
    __shared__ float ss[BB][TT][TT];
    __shared__ float sv[TT][TT];
    __shared__ float sl[192][25];
    __shared__ float smean[TT], sinv[TT];
    for (int idx = tid; idx < BB*TT*TT; idx += 192) ((float*)ss)[idx] = g_s[idx];
    for (int idx = tid; idx < TT*TT;   idx += 192) ((float*)sv)[idx] = v[idx];
    __syncthreads();
    const int b = tid / TT, i = tid % TT;
    float l[TT];
#pragma unroll
    for (int k = 0; k < TT; ++k) l[k] = 0.0f;
#pragma unroll
    for (int jj = 0; jj < TT; ++jj){
        float vij = sv[i][jj];
#pragma unroll
        for (int k = 0; k < TT; ++k) l[k] = fmaf(vij, ss[b][jj][k], l[k]);
    }
#pragma unroll
    for (int k = 0; k < TT; ++k) sl[tid][k] = l[k];
    __syncthreads();
    if (tid < TT){
        float s = 0.0f, s2 = 0.0f;
        for (int r = 0; r < 192; ++r){ float x = sl[r][tid]; s += x; s2 = fmaf(x, x, s2); }
        float m = s * (1.0f/192.0f);
        smean[tid] = m;
        sinv[tid]  = rsqrtf(s2 * (1.0f/192.0f) - m*m + 1e-5f);
    }
    __syncthreads();
    float mx = -3.4e38f;
#pragma unroll
    for (int k = 0; k < TT; ++k){
        float y = (l[k] - smean[k]) * sinv[k] * gamma[k] + beta[k];
        if ((i < 12) != (k < 12)) y -= 1e13f;
        l[k] = y;
        mx = fmaxf(mx, y);
    }
    float s = 0.0f;
#pragma unroll
    for (int k = 0; k < TT; ++k){ float e = __expf(l[k] - mx); l[k] = e; s += e; }
    float inv = 1.0f / s;
#pragma unroll
    for (int k = 0; k < TT; ++k)
        out[((size_t)b*TT + i)*TT + k] = l[k] * inv;
}

// ---------------- launch ----------------
extern "C" void kernel_launch(void* const* d_in, const int* in_sizes, int n_in,
                              void* d_out, int out_size){
    const float* seq   = (const float*)d_in[0];
    const float* w1    = (const float*)d_in[1];
    const float* w2    = (const float*)d_in[2];
    const float* Wd1   = (const float*)d_in[3];
    const float* Wd2   = (const float*)d_in[4];
    const float* w     = (const float*)d_in[5];
    const float* bbias = (const float*)d_in[6];
    const float* v     = (const float*)d_in[7];
    const float* gamma = (const float*)d_in[8];
    const float* beta  = (const float*)d_in[9];
    float* out = (float*)d_out;

    cudaFuncSetAttribute(k1_reduce, cudaFuncAttributeMaxDynamicSharedMemorySize, K1_SMEM);
    cudaFuncSetAttribute(k2b_conv2, cudaFuncAttributeMaxDynamicSharedMemorySize, K2B_SMEM);

    // k1 is the 4th launch == the ncu capture slot
    k0a_zero  <<<(BB*TT*NNODES + 255)/256, 256>>>();
    k0b_zero  <<<(BB*CC*TT + 255)/256, 256>>>();
    k0c_zero  <<<(BB*CC*TT + 255)/256, 256>>>();
    k1_reduce <<<296, 192, K1_SMEM>>>(seq, w1, w2);
    k2b_conv2 <<<128, 256, K2B_SMEM>>>(Wd2);
    k2ac_fused<<<256, 256>>>(Wd1, w);
    k2d1_attn <<<BB*TT, 128>>>(bbias);
    k2d2_final<<<1, 192>>>(v, gamma, beta, out);
}

// round 17
// speedup vs baseline: 1.0246x; 1.0246x over previous
#include <cuda_runtime.h>
#include <cstdint>

#define BB 8
#define CC 512
#define NNODES 2048
#define TT 24

#define K1_NC    4                          // n per chunk
#define K1_PITCH 96                         // words per c-row segment (4n*24t)
#define K1_TILE  (128*K1_PITCH)             // words per buffer (48 KB)
#define K1_SMEM  ((2*K1_TILE + 192) * 4)    // buffers + w2 slice + f1 stage

// k2b dynamic smem layout (floats)
#define K2B_SF    (512*26)
#define K2B_SWX   (K2B_SF)
#define K2B_SWY   (K2B_SWX + 32*65)
#define K2B_PART  (K2B_SWY + 32*65)
#define K2B_SMEM  ((K2B_PART + 8*12*32*2) * 4)

typedef unsigned long long ull;

// ---------------- scratch (static device arrays; no allocation) ----------------
__device__ float g_f1  [BB*TT*NNODES];   // f1[b][t][n]          (atomically accumulated)
__device__ float g_f2  [BB*CC*TT];       // f2[b][c][t]          (atomically accumulated)
__device__ float g_f2cT[BB*TT*CC];       // f2c transposed [b][t][c]   (plain stores)
__device__ float g_g   [BB*TT*CC];       // g[b][t][c] = f1c @ w       (red.v4 accumulated)
__device__ float g_s   [BB*TT*TT];       // sigmoid attention matrix

// ---------------- packed f32x2 helpers ----------------
__device__ __forceinline__ ull fma2(ull a, ull b, ull c){
    ull d;
    asm("fma.rn.f32x2 %0, %1, %2, %3;" : "=l"(d) : "l"(a), "l"(b), "l"(c));
    return d;
}
__device__ __forceinline__ ull add2(ull a, ull b){
    ull d;
    asm("add.rn.f32x2 %0, %1, %2;" : "=l"(d) : "l"(a), "l"(b));
    return d;
}
__device__ __forceinline__ ull pack2(float f){
    ull r;
    asm("mov.b64 %0, {%1, %1};" : "=l"(r) : "f"(f));
    return r;
}
__device__ __forceinline__ float2 unpk2(ull v){
    float2 f;
    asm("mov.b64 {%0, %1}, %2;" : "=f"(f.x), "=f"(f.y) : "l"(v));
    return f;
}

// ---------------- K0: zero all accumulated scratch ----------------
__global__ void k0_zero(){
    int idx = blockIdx.x * 256 + threadIdx.x;
    if (idx < BB*TT*NNODES) g_f1[idx] = 0.0f;
    if (idx < BB*CC*TT){
        g_f2[idx] = 0.0f;
        g_g [idx] = 0.0f;
    }
}

// ---------------- K1: fused dual weighted reduction over seq ----------------
// grid = 1024 (8b x 4ct x 32ns), block = 192, 2 blocks/SM.
// cp.async double-buffered (128c x 4n x 24t) chunks; XOR-swizzled tile.
// Chunk compute split: (A) fma accumulation for all nn, (B) 8 interleaved
// butterfly chains -> SHFL latency amortized 8-wide instead of serialized.
__device__ __forceinline__ void k1_stage(const float* gbase, float* buf, int ju, int c0s){
#pragma unroll
    for (int k2 = 0; k2 < 16; ++k2){
        const int c = c0s + 8*k2;
        const float* g = gbase + (size_t)c * (NNODES*TT);
        unsigned sa = (unsigned)__cvta_generic_to_shared(
            &buf[c*K1_PITCH + ((ju ^ (c & 7)) << 2)]);
        asm volatile("cp.async.cg.shared.global [%0], [%1], 16;" :: "r"(sa), "l"(g) : "memory");
    }
    asm volatile("cp.async.commit_group;" ::: "memory");
}

__global__ void __launch_bounds__(192, 2)
k1_reduce(const float* __restrict__ seq, const float* __restrict__ w1, const float* __restrict__ w2){
    extern __shared__ float sm[];
    float* buf0 = sm;
    float* buf1 = sm + K1_TILE;
    float* sw2n = sm + 2*K1_TILE;      // [64]
    float* f1st = sw2n + 64;           // [96]

    const int blk = blockIdx.x;
    const int b   = blk >> 7;
    const int ct  = (blk >> 5) & 3;
    const int nb  = (blk & 31) * 64;
    const int tid = threadIdx.x;
    const int w   = tid >> 5;
    const int lane= tid & 31;
    const int ju  = tid % 24;
    const int c0s = tid / 24;
    const int xm  = lane & 7;

    if (tid < 64) sw2n[tid] = w2[nb + tid];

    const float* seqbase = seq + ((size_t)(b*CC + ct*128) * NNODES + nb) * TT + ju*4;

    ull w1p[4];
#pragma unroll
    for (int kk = 0; kk < 4; ++kk) w1p[kk] = pack2(w1[ct*128 + lane + 32*kk]);

    ull acc[4][2];
#pragma unroll
    for (int kk = 0; kk < 4; ++kk){ acc[kk][0] = 0ull; acc[kk][1] = 0ull; }

    k1_stage(seqbase, buf0, ju, c0s);

    for (int ch = 0; ch < 16; ++ch){
        float* cur = (ch & 1) ? buf1 : buf0;
        if (ch < 15){
            k1_stage(seqbase + (size_t)(ch+1)*K1_NC*TT, (ch & 1) ? buf0 : buf1, ju, c0s);
            asm volatile("cp.async.wait_group 1;" ::: "memory");
        } else {
            asm volatile("cp.async.wait_group 0;" ::: "memory");
        }
        __syncthreads();   // sync(A): buffer ready; prior f1st reads done

        // ---- phase A: fma accumulation for all nn (no shuffles) ----
        ull p[K1_NC][2];
#pragma unroll
        for (int nn = 0; nn < K1_NC; ++nn){
            const ull w2p = pack2(sw2n[ch*K1_NC + nn]);
            const int so = (((6*nn + w) ^ xm) << 2);
            p[nn][0] = 0ull; p[nn][1] = 0ull;
#pragma unroll
            for (int kk = 0; kk < 4; ++kk){
                const ulonglong2 x = *reinterpret_cast<const ulonglong2*>(
                    &cur[(lane + 32*kk)*K1_PITCH + so]);
                acc[kk][0] = fma2(w2p, x.x, acc[kk][0]);
                acc[kk][1] = fma2(w2p, x.y, acc[kk][1]);
                p[nn][0] = fma2(w1p[kk], x.x, p[nn][0]);
                p[nn][1] = fma2(w1p[kk], x.y, p[nn][1]);
            }
        }
        // ---- phase B: 8 interleaved butterfly chains ----
#pragma unroll
        for (int off = 16; off > 0; off >>= 1){
#pragma unroll
            for (int nn = 0; nn < K1_NC; ++nn){
                p[nn][0] = add2(p[nn][0], __shfl_xor_sync(0xffffffffu, p[nn][0], off));
                p[nn][1] = add2(p[nn][1], __shfl_xor_sync(0xffffffffu, p[nn][1], off));
            }
        }
        if (lane == 0){
#pragma unroll
            for (int nn = 0; nn < K1_NC; ++nn){
                float2 a = unpk2(p[nn][0]), d = unpk2(p[nn][1]);
                *reinterpret_cast<float4*>(&f1st[nn*24 + w*4]) = make_float4(a.x, a.y, d.x, d.y);
            }
        }
        __syncthreads();   // sync(B): f1st complete, tile reads done

        if (tid < 96){
            const int nn = tid / 24, t = tid - nn*24;
            atomicAdd(&g_f1[((size_t)b*TT + t)*NNODES + nb + ch*K1_NC + nn], f1st[nn*24 + t]);
        }
    }

#pragma unroll
    for (int kk = 0; kk < 4; ++kk){
        const int c = ct*128 + lane + 32*kk;
        float* o = g_f2 + ((size_t)b*CC + c)*TT + w*4;
        float2 a = unpk2(acc[kk][0]), d = unpk2(acc[kk][1]);
        atomicAdd(o + 0, a.x);
        atomicAdd(o + 1, a.y);
        atomicAdd(o + 2, d.x);
        atomicAdd(o + 3, d.y);
    }
}

// ---------------- K2b: dilated conv of f2 over t, ATOMIC-FREE ----------------
__global__ void __launch_bounds__(256) k2b_conv2(const float* __restrict__ Wd2){
    extern __shared__ float smb[];
    float* sf  = smb;                    // [512][26], j = t+1, halo at 0/25
    float* swx = smb + K2B_SWX;          // [32][65]
    float* swy = smb + K2B_SWY;          // [32][65]
    ull*   part= reinterpret_cast<ull*>(smb + K2B_PART);  // [8][12][32]

    const int b  = blockIdx.x >> 4;
    const int o0 = (blockIdx.x & 15) * 32;
    const int tid   = threadIdx.x;
    const int olane = tid & 31;
    const int ig    = tid >> 5;

    for (int i = tid; i < 512; i += 256){ sf[i*26] = 0.0f; sf[i*26 + 25] = 0.0f; }
    const float* f2b = g_f2 + (size_t)b*CC*TT;
#pragma unroll
    for (int u = 0; u < 48; ++u){
        int idx = tid + u*256;
        int i = idx / 24, t = idx - i*24;
        sf[i*26 + t + 1] = f2b[idx];
    }

    ull acc[12];
#pragma unroll
    for (int u = 0; u < 12; ++u) acc[u] = 0ull;

    const float2* wsrc = reinterpret_cast<const float2*>(Wd2);
    for (int r = 0; r < 8; ++r){
        __syncthreads();
#pragma unroll
        for (int u = 0; u < 8; ++u){
            int idx = tid + u*256;
            int oo = idx >> 6, iz = idx & 63;
            float2 wv = wsrc[(size_t)(o0+oo)*CC + r*64 + iz];
            swx[oo*65 + iz] = wv.x;
            swy[oo*65 + iz] = wv.y;
        }
        __syncthreads();
#pragma unroll
        for (int q = 0; q < 8; ++q){
            const int li = ig*8 + q;
            const int i  = r*64 + li;
            ull wx = pack2(swx[olane*65 + li]);
            ull wy = pack2(swy[olane*65 + li]);
            const ull* R = reinterpret_cast<const ull*>(&sf[i*26]);
#pragma unroll
            for (int u = 0; u < 12; ++u){
                acc[u] = fma2(wx, R[u], acc[u]);
                acc[u] = fma2(wy, R[u+1], acc[u]);
            }
        }
    }
    __syncthreads();
#pragma unroll
    for (int u = 0; u < 12; ++u) part[(ig*12 + u)*32 + olane] = acc[u];
    __syncthreads();
    const int oo = tid & 31;
    const int tb = (tid >> 5) * 3;
#pragma unroll
    for (int q = 0; q < 3; ++q){
        const int t = tb + q;
        const int ttp = t >> 1, half = t & 1;
        float s = 0.0f;
#pragma unroll
        for (int g2 = 0; g2 < 8; ++g2){
            float2 pp = unpk2(part[(g2*12 + ttp)*32 + oo]);
            s += half ? pp.y : pp.x;
        }
        g_f2cT[(size_t)b*TT*CC + (size_t)t*CC + o0 + oo] = s;
    }
}

// ---------------- K2ac: FUSED dilated-conv(f1) + GEMM, cp.async-staged w ----------------
__global__ void __launch_bounds__(256, 2) k2ac_fused(const float* __restrict__ Wd1,
                                                     const float* __restrict__ w){
    __shared__ __align__(16) float pool[8192];   // phase1: s1|sw ; phase2: wbuf0|wbuf1
    __shared__ ull sf2T[64][26];                 // splatted f1c tile, [nl][t] (+pad)

    const int b  = blockIdx.x >> 5;
    const int n0 = (blockIdx.x & 31) * 64;
    const int tid = threadIdx.x;

    float* s1 = pool;                 // [24][66]
    float* sw = pool + TT*66;         // [24][48]

    for (int idx = tid; idx < TT*48; idx += 256) sw[idx] = Wd1[idx];
    for (int idx = tid; idx < TT*66; idx += 256){
        int i = idx / 66, j = idx - i*66;
        int n = n0 + j - 1;
        s1[i*66 + j] = (n >= 0 && n < NNODES) ? g_f1[((size_t)b*TT + i)*NNODES + n] : 0.0f;
    }
    __syncthreads();
#pragma unroll
    for (int u = 0; u < 6; ++u){
        int idx = tid + u*256;           // 0..1535
        int t = idx >> 6, nl = idx & 63;
        float acc = 0.0f;
#pragma unroll
        for (int i = 0; i < TT; ++i)
            acc += s1[i*66 + nl] * sw[t*48 + 2*i] + s1[i*66 + nl+2] * sw[t*48 + 2*i+1];
        sf2T[nl][t] = pack2(acc);
    }
    __syncthreads();                     // phase1 reads done -> pool reusable

    const int th = tid >> 7;             // t-half 0..1
    const int cq = tid & 127;            // c-quad
    ull acc[12][2];
#pragma unroll
    for (int tt = 0; tt < 12; ++tt){ acc[tt][0] = 0ull; acc[tt][1] = 0ull; }

    const float* wchunk = w + (size_t)n0*CC;

#pragma unroll
    for (int u = 0; u < 4; ++u){
        int idx = tid + u*256;
        int rw = idx >> 7, c4 = idx & 127;
        unsigned sa = (unsigned)__cvta_generic_to_shared(&pool[rw*512 + c4*4]);
        asm volatile("cp.async.cg.shared.global [%0], [%1], 16;"
                     :: "r"(sa), "l"(wchunk + (size_t)rw*CC + c4*4) : "memory");
    }
    asm volatile("cp.async.commit_group;" ::: "memory");

    for (int r = 0; r < 8; ++r){
        const float* cur = (r & 1) ? (pool + 4096) : pool;
        if (r < 7){
            float* nxt = (r & 1) ? pool : (pool + 4096);
#pragma unroll
            for (int u = 0; u < 4; ++u){
                int idx = tid + u*256;
                int rw = idx >> 7, c4 = idx & 127;
                unsigned sa = (unsigned)__cvta_generic_to_shared(&nxt[rw*512 + c4*4]);
                asm volatile("cp.async.cg.shared.global [%0], [%1], 16;"
                             :: "r"(sa), "l"(wchunk + (size_t)((r+1)*8 + rw)*CC + c4*4) : "memory");
            }
            asm volatile("cp.async.commit_group;" ::: "memory");
            asm volatile("cp.async.wait_group 1;" ::: "memory");
        } else {
            asm volatile("cp.async.wait_group 0;" ::: "memory");
        }
        __syncthreads();                 // tile r visible to all
#pragma unroll
        for (int q = 0; q < 8; ++q){
            const ulonglong2 wp = *reinterpret_cast<const ulonglong2*>(&cur[q*512 + 4*cq]);
            const int nl = r*8 + q;
            const ulonglong2* fr = reinterpret_cast<const ulonglong2*>(&sf2T[nl][th*12]);
#pragma unroll
            for (int p = 0; p < 6; ++p){
                ulonglong2 fv = fr[p];       // LDS.128 broadcast
                acc[2*p  ][0] = fma2(fv.x, wp.x, acc[2*p  ][0]);
                acc[2*p  ][1] = fma2(fv.x, wp.y, acc[2*p  ][1]);
                acc[2*p+1][0] = fma2(fv.y, wp.x, acc[2*p+1][0]);
                acc[2*p+1][1] = fma2(fv.y, wp.y, acc[2*p+1][1]);
            }
        }
        __syncthreads();                 // compute done before next overwrite
    }

#pragma unroll
    for (int tt = 0; tt < 12; ++tt){
        float2 a = unpk2(acc[tt][0]), d = unpk2(acc[tt][1]);
        float* gp = &g_g[((size_t)b*TT + th*12 + tt)*CC + 4*cq];
        asm volatile("red.global.add.v4.f32 [%0], {%1,%2,%3,%4};"
                     :: "l"(gp), "f"(a.x), "f"(a.y), "f"(d.x), "f"(d.y) : "memory");
    }
}

// ---------------- K2d1: s[b,j,k] = sigmoid(g[b,j,:] . f2cT[b,k,:] + bias) ----------------
__global__ void __launch_bounds__(128) k2d1_attn(const float* __restrict__ bbias){
    const int b = blockIdx.x / 24;
    const int jj = blockIdx.x % 24;
    const int tid  = threadIdx.x;
    const int wrp  = tid >> 5;
    const int lane = tid & 31;
    __shared__ __align__(16) float sg[CC];
    const float* grow = g_g + ((size_t)b*TT + jj)*CC;
#pragma unroll
    for (int u = 0; u < 4; ++u) sg[tid + u*128] = grow[tid + u*128];
    __syncthreads();
    const ull* sg2 = reinterpret_cast<const ull*>(sg);
    const ull* f0  = reinterpret_cast<const ull*>(g_f2cT + ((size_t)b*TT + wrp*6)*CC);
    ull acc[6] = {0ull,0ull,0ull,0ull,0ull,0ull};
#pragma unroll
    for (int it = 0; it < 8; ++it){
        ull gv = sg2[lane + it*32];
#pragma unroll
        for (int kk = 0; kk < 6; ++kk)
            acc[kk] = fma2(f0[(size_t)kk*256 + lane + it*32], gv, acc[kk]);
    }
#pragma unroll
    for (int kk = 0; kk < 6; ++kk)
#pragma unroll
        for (int off = 16; off > 0; off >>= 1)
            acc[kk] = add2(acc[kk], __shfl_xor_sync(0xffffffffu, acc[kk], off));
    if (lane < 6){
        int k = wrp*6 + lane;
        float2 aa = unpk2(acc[lane]);
        float sv = aa.x + aa.y + bbias[jj*TT + k];
        g_s[((size_t)b*TT + jj)*TT + k] = 1.0f/(1.0f + __expf(-sv));
    }
}

// ---------------- K2d2: l = v @ s; BN + mask + softmax (single block) ----------------
__global__ void k2d2_final(const float* __restrict__ v, const float* __restrict__ gamma,
                           const float* __restrict__ beta, float* __restrict__ out){
    const int tid = threadIdx.x;
    __shared__ float ss[BB][TT][TT];
    __shared__ float sv[TT][TT];
    __shared__ float sl[192][25];
    __shared__ float smean[TT], sinv[TT];
    for (int idx = tid; idx < BB*TT*TT; idx += 192) ((float*)ss)[idx] = g_s[idx];
    for (int idx = tid; idx < TT*TT;   idx += 192) ((float*)sv)[idx] = v[idx];
    __syncthreads();
    const int b = tid / TT, i = tid % TT;
    float l[TT];
#pragma unroll
    for (int k = 0; k < TT; ++k) l[k] = 0.0f;
#pragma unroll
    for (int jj = 0; jj < TT; ++jj){
        float vij = sv[i][jj];
#pragma unroll
        for (int k = 0; k < TT; ++k) l[k] = fmaf(vij, ss[b][jj][k], l[k]);
    }
#pragma unroll
    for (int k = 0; k < TT; ++k) sl[tid][k] = l[k];
    __syncthreads();
    if (tid < TT){
        float s = 0.0f, s2 = 0.0f;
        for (int r = 0; r < 192; ++r){ float x = sl[r][tid]; s += x; s2 = fmaf(x, x, s2); }
        float m = s * (1.0f/192.0f);
        smean[tid] = m;
        sinv[tid]  = rsqrtf(s2 * (1.0f/192.0f) - m*m + 1e-5f);
    }
    __syncthreads();
    float mx = -3.4e38f;
#pragma unroll
    for (int k = 0; k < TT; ++k){
        float y = (l[k] - smean[k]) * sinv[k] * gamma[k] + beta[k];
        if ((i < 12) != (k < 12)) y -= 1e13f;
        l[k] = y;
        mx = fmaxf(mx, y);
    }
    float s = 0.0f;
#pragma unroll
    for (int k = 0; k < TT; ++k){ float e = __expf(l[k] - mx); l[k] = e; s += e; }
    float inv = 1.0f / s;
#pragma unroll
    for (int k = 0; k < TT; ++k)
        out[((size_t)b*TT + i)*TT + k] = l[k] * inv;
}

// ---------------- launch ----------------
extern "C" void kernel_launch(void* const* d_in, const int* in_sizes, int n_in,
                              void* d_out, int out_size){
    const float* seq   = (const float*)d_in[0];
    const float* w1    = (const float*)d_in[1];
    const float* w2    = (const float*)d_in[2];
    const float* Wd1   = (const float*)d_in[3];
    const float* Wd2   = (const float*)d_in[4];
    const float* w     = (const float*)d_in[5];
    const float* bbias = (const float*)d_in[6];
    const float* v     = (const float*)d_in[7];
    const float* gamma = (const float*)d_in[8];
    const float* beta  = (const float*)d_in[9];
    float* out = (float*)d_out;

    cudaFuncSetAttribute(k1_reduce, cudaFuncAttributeMaxDynamicSharedMemorySize, K1_SMEM);
    cudaFuncSetAttribute(k2b_conv2, cudaFuncAttributeMaxDynamicSharedMemorySize, K2B_SMEM);

    k0_zero   <<<(BB*TT*NNODES + 255)/256, 256>>>();
    k1_reduce <<<1024, 192, K1_SMEM>>>(seq, w1, w2);
    k2b_conv2 <<<128, 256, K2B_SMEM>>>(Wd2);
    k2ac_fused<<<256, 256>>>(Wd1, w);
    k2d1_attn <<<BB*TT, 128>>>(bbias);
    k2d2_final<<<1, 192>>>(v, gamma, beta, out);
}